// round 8
// baseline (speedup 1.0000x reference)
#include <cuda_runtime.h>

#define BB 128
#define GG 20000
#define NELEM (BB * GG)        // 2,560,000
#define NPAIR (NELEM / 2)      // 1,280,000
#define HID 64
#define KB 9                   // NUM_BINS - 1
#define NSEG (HID + 1)         // 65 piecewise-linear segments
#define ACROW 10               // padded row: 10 float2 = 80B
#define LOG2E 1.44269504088896340736f

// Piecewise-linear representation: segment s -> logit_k*log2(e) = A*x + C
__device__ float  g_T[HID];            // sorted breakpoints
__device__ float2 g_AC[NSEG * ACROW];  // (A, C), pre-scaled by log2(e)

__device__ __forceinline__ float ex2(float v) {
    float r;
    asm("ex2.approx.f32 %0, %1;" : "=f"(r) : "f"(v));
    return r;
}

// XOR swizzle at float4 granularity: kills STS bank conflicts on the write
// side (stride-5 rows) while keeping the linear read side conflict-free.
__device__ __forceinline__ int swz(int i) { return i ^ ((i >> 3) & 7); }

// ---------------------------------------------------------------------------
// Precompute kernel: 1 block, 640 threads.
// ---------------------------------------------------------------------------
__global__ void precompute_kernel(const float* __restrict__ W1,
                                  const float* __restrict__ b1,
                                  const float* __restrict__ W2,
                                  const float* __restrict__ b2) {
    __shared__ float w1s[HID], b1s[HID], W2s[HID * KB], b2s[KB];
    __shared__ float t[HID], srt[HID];
    int tid = threadIdx.x;

    if (tid < HID)      { w1s[tid] = W1[tid]; b1s[tid] = b1[tid]; }
    if (tid < HID * KB) { W2s[tid] = W2[tid]; }
    if (tid < KB)       { b2s[tid] = b2[tid]; }
    __syncthreads();

    if (tid < HID) {
        float w = w1s[tid], b = b1s[tid];
        float tv = (w != 0.0f) ? (-b / w) : 1e30f;
        if (!(tv > -1e30f)) tv = -1e30f;
        if (tv > 1e30f)     tv = 1e30f;
        t[tid] = tv;
    }
    __syncthreads();

    if (tid < HID) {   // rank sort (64 elements)
        float tv = t[tid];
        int rank = 0;
        #pragma unroll 8
        for (int i = 0; i < HID; i++) {
            float o = t[i];
            rank += (o < tv || (o == tv && i < tid)) ? 1 : 0;
        }
        srt[rank] = tv;
    }
    __syncthreads();

    if (tid < HID) g_T[tid] = srt[tid];

    if (tid < NSEG * KB) {
        int s = tid / KB;
        int k = tid - s * KB;
        float xm;
        if (s == 0)        xm = srt[0] - 1.0f;
        else if (s == HID) xm = srt[HID - 1] + 1.0f;
        else               xm = 0.5f * srt[s - 1] + 0.5f * srt[s];

        float A = 0.0f, C = b2s[k];
        #pragma unroll 4
        for (int j = 0; j < HID; j++) {
            float w = w1s[j], b = b1s[j];
            float h = fmaf(xm, w, b);
            float c = (h >= 0.0f) ? 1.0f : 0.01f;
            float wv = W2s[j * KB + k];
            A = fmaf(c * w, wv, A);
            C = fmaf(c * b, wv, C);
        }
        g_AC[s * ACROW + k] = make_float2(A * LOG2E, C * LOG2E);
    }
}

// ---------------------------------------------------------------------------
// Main kernel: one element pair per thread; swizzled SMEM staging so every
// global store is fully coalesced and every STS/LDS runs at the 4-phase floor.
// ---------------------------------------------------------------------------
__device__ __forceinline__ void process_one(float x,
                                            const float* __restrict__ sT,
                                            const float2* __restrict__ sAC,
                                            float* o /*10*/, float& mask) {
    if (x == 0.0f) {
        o[0] = 1.0f;
        #pragma unroll
        for (int k = 0; k < KB; k++) o[k + 1] = 0.0f;
        mask = 0.0f;
    } else {
        // branchless lower_bound over 64 sorted breakpoints (active lanes only)
        int pos = 0;
        #pragma unroll
        for (int step = 32; step >= 1; step >>= 1)
            if (sT[pos + step - 1] < x) pos += step;

        const float2* row = sAC + pos * ACROW;
        float4 r0 = *reinterpret_cast<const float4*>(row);
        float4 r1 = *reinterpret_cast<const float4*>(row + 2);
        float4 r2 = *reinterpret_cast<const float4*>(row + 4);
        float4 r3 = *reinterpret_cast<const float4*>(row + 6);
        float2 r4 = row[8];

        // logits bounded; coefficients pre-scaled by log2(e) -> raw ex2
        float e0 = ex2(fmaf(r0.x, x, r0.y));
        float e1 = ex2(fmaf(r0.z, x, r0.w));
        float e2 = ex2(fmaf(r1.x, x, r1.y));
        float e3 = ex2(fmaf(r1.z, x, r1.w));
        float e4 = ex2(fmaf(r2.x, x, r2.y));
        float e5 = ex2(fmaf(r2.z, x, r2.w));
        float e6 = ex2(fmaf(r3.x, x, r3.y));
        float e7 = ex2(fmaf(r3.z, x, r3.w));
        float e8 = ex2(fmaf(r4.x, x, r4.y));

        float s = (((e0 + e1) + (e2 + e3)) + ((e4 + e5) + (e6 + e7))) + e8;
        float inv = __fdividef(1.0f, s);

        o[0] = 0.0f;
        o[1] = e0 * inv;  o[2] = e1 * inv;  o[3] = e2 * inv;
        o[4] = e3 * inv;  o[5] = e4 * inv;  o[6] = e5 * inv;
        o[7] = e6 * inv;  o[8] = e7 * inv;  o[9] = e8 * inv;
        mask = 1.0f;
    }
}

__global__ void __launch_bounds__(256) expr_quant_kernel(const float* __restrict__ expr,
                                                         float* __restrict__ out) {
    __shared__ float  sT[HID];
    __shared__ float2 sAC[NSEG * ACROW];
    __shared__ float4 stage[256 * 5];   // 20 KB, accessed via swz()

    int tid = threadIdx.x;
    size_t pairBase = (size_t)blockIdx.x * 256;
    size_t pair = pairBase + tid;

    // prefetch input before smem preload to overlap LDG latency
    float2 xv = *reinterpret_cast<const float2*>(expr + 2 * pair);

    if (tid < HID) sT[tid] = g_T[tid];
    for (int i = tid; i < NSEG * ACROW; i += 256) sAC[i] = g_AC[i];
    __syncthreads();

    float o[20];
    float m0, m1;
    process_one(xv.x, sT, sAC, o,      m0);
    process_one(xv.y, sT, sAC, o + 10, m1);

    // mask store (coalesced 8B/lane)
    *reinterpret_cast<float2*>(out + (size_t)NELEM * 10 + 2 * pair) = make_float2(m0, m1);

    // stage 5 float4s per thread at swizzled slots (write side ~conflict-free)
    int base = tid * 5;
    stage[swz(base + 0)] = make_float4(o[0],  o[1],  o[2],  o[3]);
    stage[swz(base + 1)] = make_float4(o[4],  o[5],  o[6],  o[7]);
    stage[swz(base + 2)] = make_float4(o[8],  o[9],  o[10], o[11]);
    stage[swz(base + 3)] = make_float4(o[12], o[13], o[14], o[15]);
    stage[swz(base + 4)] = make_float4(o[16], o[17], o[18], o[19]);

    __syncthreads();

    // coalesced copy-out: read side of swz() is conflict-free for linear i
    float4* dst = reinterpret_cast<float4*>(out + pairBase * 20);
    #pragma unroll
    for (int m = 0; m < 5; m++) {
        int i = tid + 256 * m;
        dst[i] = stage[swz(i)];
    }
}

// ---------------------------------------------------------------------------
extern "C" void kernel_launch(void* const* d_in, const int* in_sizes, int n_in,
                              void* d_out, int out_size) {
    const float* expr = (const float*)d_in[0];
    const float* W1   = (const float*)d_in[1];
    const float* b1   = (const float*)d_in[2];
    const float* W2   = (const float*)d_in[3];
    const float* b2   = (const float*)d_in[4];
    float* out = (float*)d_out;

    precompute_kernel<<<1, 640>>>(W1, b1, W2, b2);
    expr_quant_kernel<<<NPAIR / 256, 256>>>(expr, out);
}

// round 9
// speedup vs baseline: 1.4890x; 1.4890x over previous
#include <cuda_runtime.h>

#define BB 128
#define GG 20000
#define NELEM (BB * GG)        // 2,560,000
#define HID 64
#define KB 9                   // NUM_BINS - 1
#define NSEG (HID + 1)         // 65 piecewise-linear segments
#define ACROW 10               // padded row: 10 float2 = 80B
#define NTAB 4096
#define LOG2E 1.44269504088896340736f
#define TPB 512                // threads (= elements) per block

// Piecewise-linear representation: segment s -> logit_k*log2(e) = A*x + C
__device__ float         g_T[HID];             // sorted breakpoints
__device__ float2        g_AC[NSEG * ACROW];   // (A, C), pre-scaled by log2(e)
__device__ unsigned char g_Tab[NTAB];          // lower-bound at bucket start

__device__ __forceinline__ float ex2(float v) {
    float r;
    asm("ex2.approx.f32 %0, %1;" : "=f"(r) : "f"(v));
    return r;
}

__device__ __forceinline__ unsigned int mono_key(float x) {
    unsigned int u = __float_as_uint(x);
    return ((int)u < 0) ? ~u : (u | 0x80000000u);
}

// ---------------------------------------------------------------------------
// Precompute kernel: 1 block, 640 threads. Table built with binary search
// (cheap), not linear scans.
// ---------------------------------------------------------------------------
__global__ void precompute_kernel(const float* __restrict__ W1,
                                  const float* __restrict__ b1,
                                  const float* __restrict__ W2,
                                  const float* __restrict__ b2) {
    __shared__ float w1s[HID], b1s[HID], W2s[HID * KB], b2s[KB];
    __shared__ float t[HID], srt[HID];
    __shared__ unsigned int ku[HID];
    int tid = threadIdx.x;

    if (tid < HID)      { w1s[tid] = W1[tid]; b1s[tid] = b1[tid]; }
    if (tid < HID * KB) { W2s[tid] = W2[tid]; }
    if (tid < KB)       { b2s[tid] = b2[tid]; }
    __syncthreads();

    if (tid < HID) {
        float w = w1s[tid], b = b1s[tid];
        float tv = (w != 0.0f) ? (-b / w) : 1e30f;
        if (!(tv > -1e30f)) tv = -1e30f;
        if (tv > 1e30f)     tv = 1e30f;
        t[tid] = tv;
    }
    __syncthreads();

    if (tid < HID) {   // rank sort (64 elements)
        float tv = t[tid];
        int rank = 0;
        #pragma unroll 8
        for (int i = 0; i < HID; i++) {
            float o = t[i];
            rank += (o < tv || (o == tv && i < tid)) ? 1 : 0;
        }
        srt[rank] = tv;
    }
    __syncthreads();

    if (tid < HID) { g_T[tid] = srt[tid]; ku[tid] = mono_key(srt[tid]); }

    if (tid < NSEG * KB) {
        int s = tid / KB;
        int k = tid - s * KB;
        float xm;
        if (s == 0)        xm = srt[0] - 1.0f;
        else if (s == HID) xm = srt[HID - 1] + 1.0f;
        else               xm = 0.5f * srt[s - 1] + 0.5f * srt[s];

        float A = 0.0f, C = b2s[k];
        #pragma unroll 4
        for (int j = 0; j < HID; j++) {
            float w = w1s[j], b = b1s[j];
            float h = fmaf(xm, w, b);
            float c = (h >= 0.0f) ? 1.0f : 0.01f;
            float wv = W2s[j * KB + k];
            A = fmaf(c * w, wv, A);
            C = fmaf(c * b, wv, C);
        }
        g_AC[s * ACROW + k] = make_float2(A * LOG2E, C * LOG2E);
    }
    __syncthreads();

    // g_Tab[i] = #(keys < (i<<20)) via binary search on sorted ku
    for (int i = tid; i < NTAB; i += 640) {
        unsigned int bkey = (unsigned int)i << 20;
        int pos = 0;
        #pragma unroll
        for (int step = 32; step >= 1; step >>= 1)
            if (ku[pos + step - 1] < bkey) pos += step;
        g_Tab[i] = (unsigned char)pos;
    }
}

// ---------------------------------------------------------------------------
// Main kernel: one thread per ELEMENT. Coalesced zero-pattern prefill of the
// block's whole slice, then sparse predicated overwrite for nonzeros (~10%).
// All tables read via __ldg (stay hot in L1; no per-block smem preload).
// ---------------------------------------------------------------------------
__device__ __forceinline__ float4 zpat(int r) {  // r = (float4 index) % 5
    return make_float4(r == 0 ? 1.0f : 0.0f, 0.0f,
                       r == 2 ? 1.0f : 0.0f, 0.0f);
}

__global__ void __launch_bounds__(TPB) expr_quant_kernel(const float* __restrict__ expr,
                                                         float* __restrict__ out) {
    int tid = threadIdx.x;
    size_t eBase = (size_t)blockIdx.x * TPB;

    float x = expr[eBase + tid];                 // coalesced 4B/lane

    // ---- coalesced zero-pattern prefill: TPB elements = TPB*10 floats = 1280 f4
    float4* dst = reinterpret_cast<float4*>(out + eBase * 10);
    {
        int i0 = tid;
        int i1 = tid + TPB;
        int i2 = tid + 2 * TPB;
        dst[i0] = zpat(i0 % 5);
        dst[i1] = zpat(i1 % 5);
        if (i2 < TPB * 10 / 4) dst[i2] = zpat(i2 % 5);
    }

    // mask (coalesced 4B/lane)
    float m = (x != 0.0f) ? 1.0f : 0.0f;
    out[(size_t)NELEM * 10 + eBase + tid] = m;

    __syncthreads();   // prefill must land before sparse overwrite

    if (x != 0.0f) {
        // bucket lookup + exact refinement
        int pos = __ldg(&g_Tab[mono_key(x) >> 20]);
        while (pos < HID && __ldg(&g_T[pos]) < x) pos++;

        const float4* row = reinterpret_cast<const float4*>(g_AC + pos * ACROW);
        float4 r0 = __ldg(row + 0);
        float4 r1 = __ldg(row + 1);
        float4 r2 = __ldg(row + 2);
        float4 r3 = __ldg(row + 3);
        float2 r4 = __ldg(reinterpret_cast<const float2*>(row + 4));

        float e0 = ex2(fmaf(r0.x, x, r0.y));
        float e1 = ex2(fmaf(r0.z, x, r0.w));
        float e2 = ex2(fmaf(r1.x, x, r1.y));
        float e3 = ex2(fmaf(r1.z, x, r1.w));
        float e4 = ex2(fmaf(r2.x, x, r2.y));
        float e5 = ex2(fmaf(r2.z, x, r2.w));
        float e6 = ex2(fmaf(r3.x, x, r3.y));
        float e7 = ex2(fmaf(r3.z, x, r3.w));
        float e8 = ex2(fmaf(r4.x, x, r4.y));

        float s = (((e0 + e1) + (e2 + e3)) + ((e4 + e5) + (e6 + e7))) + e8;
        float inv = __fdividef(1.0f, s);

        // 10-float row at 40B stride: always 8B-aligned -> 5x STG.64
        float2* q = reinterpret_cast<float2*>(out + (eBase + tid) * 10);
        q[0] = make_float2(0.0f,     e0 * inv);
        q[1] = make_float2(e1 * inv, e2 * inv);
        q[2] = make_float2(e3 * inv, e4 * inv);
        q[3] = make_float2(e5 * inv, e6 * inv);
        q[4] = make_float2(e7 * inv, e8 * inv);
    }
}

// ---------------------------------------------------------------------------
extern "C" void kernel_launch(void* const* d_in, const int* in_sizes, int n_in,
                              void* d_out, int out_size) {
    const float* expr = (const float*)d_in[0];
    const float* W1   = (const float*)d_in[1];
    const float* b1   = (const float*)d_in[2];
    const float* W2   = (const float*)d_in[3];
    const float* b2   = (const float*)d_in[4];
    float* out = (float*)d_out;

    precompute_kernel<<<1, 640>>>(W1, b1, W2, b2);
    expr_quant_kernel<<<NELEM / TPB, TPB>>>(expr, out);
}